// round 14
// baseline (speedup 1.0000x reference)
#include <cuda_runtime.h>
#include <cuda_bf16.h>
#include <cstdint>

#define STRD 313
// staging: 3 bufs x 2 planes
#define OFF_LS   0          // 3*2*4992  = 29952
#define OFF_RS   29952      // 3*2*7392  = 44352
#define OFF_COST 74304      // 61360
#define OFF_P    135664     // 61360
#define OFF_ENT  197024
#define OFF_PREV 198304
#define OFF_NEXT 199584
#define OFF_SEG  200864
#define OFF_RED  202048
#define SMEM_BYTES 202240

#define NTHR 320

__device__ float g_row[256];
__device__ unsigned g_ticket;

// L staging: per-128B-row slot rotation; conflict-free across xg, broadcast across dg.
__device__ __forceinline__ int rotL(int j) {
    return (((j & ~7) | ((j + (j >> 3)) & 7)) << 4);
}
// R staging: 2 pad units every 7 -> dg stride (dj=-7) maps to -9 == -1 mod 8.
__device__ __forceinline__ int padR(int j) {
    return ((j + 2 * (j / 7)) << 4);
}

__device__ __forceinline__ void cp16(uint32_t dst, const void* src) {
    asm volatile("cp.async.cg.shared.global [%0], [%1], 16;\n" :: "r"(dst), "l"(src));
}

__device__ __forceinline__ float col_entropy(const float* cost, int x) {
    int dmax = x < 48 ? x : 48;
    const float* c = cost + x;
    float m = c[0];
    for (int d = 1; d <= dmax; d++) m = fmaxf(m, c[d * STRD]);
    float S = 0.f;
    for (int d = 0; d <= dmax; d++) S += expf((c[d * STRD] - m) * 10.0f);
    float logS = logf(S), invS = 1.0f / S;
    float thr = logS - 18.420681f;
    float acc = 0.f;
    for (int d = 0; d <= dmax; d++) {
        float l = (c[d * STRD] - m) * 10.0f;
        if (l >= thr) { float p = expf(l) * invS; acc -= p * (l - logS); }
        else acc += 1.8420681e-7f;
    }
    acc += (float)(48 - dmax) * 1.8420681e-7f;
    if (dmax == 0) return 0.f;
    float e = acc / (logf((float)(dmax + 1)) + 1e-8f);
    return fminf(1.0f, fmaxf(0.0f, e));
}

__device__ __forceinline__ void extents(const float* ent, int* prevv, int* nextv, int tid) {
    int wid = tid >> 5, lane = tid & 31;
    if (wid == 0) {
        int carry = -1;
        for (int s = 0; s < 10; s++) {
            int idx = s * 32 + lane;
            int v = (idx < 312 && ent[idx] <= 0.6f) ? idx : -1;
            #pragma unroll
            for (int o = 1; o < 32; o <<= 1) {
                int t = __shfl_up_sync(0xffffffffu, v, o);
                if (lane >= o) v = max(v, t);
            }
            v = max(v, carry);
            if (idx < 312) prevv[idx] = v;
            carry = __shfl_sync(0xffffffffu, v, 31);
        }
    } else if (wid == 1) {
        int carry = 312;
        for (int s = 0; s < 10; s++) {
            int idx = 311 - (s * 32 + lane);
            int v = (idx >= 0 && ent[idx] <= 0.6f) ? idx : 312;
            #pragma unroll
            for (int o = 1; o < 32; o <<= 1) {
                int t = __shfl_up_sync(0xffffffffu, v, o);
                if (lane >= o) v = min(v, t);
            }
            v = min(v, carry);
            if (idx >= 0) nextv[idx] = v;
            carry = __shfl_sync(0xffffffffu, v, 31);
        }
    }
}

__device__ __forceinline__ void prefix_scan(const float* cost, float* P, float* segS, int tid) {
    int d = tid / 6, seg = tid - d * 6;
    if (tid < 294) {
        int xs = seg * 52;
        const float* c = cost + d * STRD;
        float* p = P + d * STRD;
        float s = 0.f;
        for (int x = xs; x < xs + 52; x++) { if (x >= d) s += c[x]; p[x] = s; }
        segS[tid] = s;
    }
    __syncthreads();
    if (tid < 294 && seg > 0) {
        float off = 0.f;
        for (int q = 0; q < seg; q++) off += segS[d * 6 + q];
        float* p = P + d * STRD;
        for (int x = seg * 52; x < seg * 52 + 52; x++) p[x] += off;
    }
    __syncthreads();
}

__device__ __forceinline__ void get_ab(const int* prevv, const int* nextv, int x, int& a, int& b) {
    int Lr = x - prevv[x] - 1; if (Lr < 0) Lr = 0;
    int Rr = nextv[x] - x - 1; if (Rr < 0) Rr = 0;
    a = x - Lr; if (a < x - 12) a = x - 12;
    b = x + Rr; if (b > x + 12) b = x + 12;
    if (b > 311) b = 311;
}

// stage 2 k-slices (channels 8*it .. 8*it+7) into buf it%3, one commit group
__device__ __forceinline__ void issue_chunk(const float* Lrow, const float* Rrow,
                                            uint32_t sb, int tid, int it, int rdst) {
    int buf = it % 3;
    if (tid < 312) {
        const float* lsrc = Lrow + (size_t)tid * 384 + it * 8;
        const float* rsrc = Rrow + (size_t)tid * 384 + it * 8;
        uint32_t ld = sb + OFF_LS + buf * 9984 + rotL(tid);
        uint32_t rd = sb + OFF_RS + buf * 14784 + rdst;
        cp16(ld, lsrc);            cp16(ld + 4992, lsrc + 4);
        cp16(rd, rsrc);            cp16(rd + 7392, rsrc + 4);
    }
    asm volatile("cp.async.commit_group;\n" ::: "memory");
}

__global__ void __launch_bounds__(NTHR, 1)
loss_row_kernel(const float* __restrict__ fL, const float* __restrict__ fR,
                const float* __restrict__ stu, float* __restrict__ out) {
    extern __shared__ __align__(128) char smem[];
    float* cost  = (float*)(smem + OFF_COST);
    float* P     = (float*)(smem + OFF_P);
    float* ent   = (float*)(smem + OFF_ENT);
    int*   prevv = (int*)(smem + OFF_PREV);
    int*   nextv = (int*)(smem + OFF_NEXT);
    float* segS  = (float*)(smem + OFF_SEG);
    float* redN  = (float*)(smem + OFF_RED);
    float* redC  = redN + 10;

    const int tid = threadIdx.x;
    const int row = blockIdx.x;
    const int b = row >> 5, h = 64 + (row & 31);
    const float* Lrow   = fL  + (size_t)(b * 96 + h) * (312 * 384);
    const float* Rrow   = fR  + (size_t)(b * 96 + h) * (312 * 384);
    const float* stuRow = stu + (size_t)(b * 96 + h) * 312;
    const uint32_t sb = (uint32_t)__cvta_generic_to_shared(smem);

    const int rdst = padR(tid + 48);

    for (int t = tid; t < 6 * 48; t += NTHR) {      // zero R pads (x-d < 0), 3 bufs x 2 planes
        int pl = t / 48, j = t - pl * 48;
        int buf = pl >> 1, p = pl & 1;
        *(float4*)(smem + OFF_RS + buf * 14784 + p * 7392 + padR(j)) =
            make_float4(0.f, 0.f, 0.f, 0.f);
    }

    const int xg = tid / 7, dg = tid - xg * 7;
    const bool act = (tid < 273);                   // 39 x-groups * 7 d-groups
    const int x0 = xg * 8, dbase = dg * 7;
    const int J0 = x0 - dbase + 42;

    int lOff[8], rOff[14];
    #pragma unroll
    for (int i = 0; i < 8; i++)  lOff[i] = rotL(x0 + i);
    #pragma unroll
    for (int m = 0; m < 14; m++) rOff[m] = padR(J0 + m);

    float acc[8][7];
    #pragma unroll
    for (int i = 0; i < 8; i++)
        #pragma unroll
        for (int dd = 0; dd < 7; dd++) acc[i][dd] = 0.f;

    issue_chunk(Lrow, Rrow, sb, tid, 0, rdst);
    issue_chunk(Lrow, Rrow, sb, tid, 1, rdst);

    for (int it = 0; it < 48; it++) {
        asm volatile("cp.async.wait_group 1;\n" ::: "memory");
        __syncthreads();
        // refill buf (it+2)%3: all warps finished reading it at iter it-1
        if (it + 2 < 48) issue_chunk(Lrow, Rrow, sb, tid, it + 2, rdst);
        else asm volatile("cp.async.commit_group;\n" ::: "memory");
        if (act) {
            int buf = it % 3;
            #pragma unroll
            for (int p = 0; p < 2; p++) {
                const char* lb = smem + OFF_LS + buf * 9984 + p * 4992;
                const char* rb = smem + OFF_RS + buf * 14784 + p * 7392;
                float4 Lv[8];
                #pragma unroll
                for (int i = 0; i < 8; i++) Lv[i] = *(const float4*)(lb + lOff[i]);
                #pragma unroll
                for (int m = 0; m < 14; m++) {
                    float4 r = *(const float4*)(rb + rOff[m]);
                    #pragma unroll
                    for (int i = 0; i < 8; i++) {
                        const int dd = i - m + 6;
                        if (dd >= 0 && dd < 7) {
                            float a = acc[i][dd];
                            a = fmaf(Lv[i].x, r.x, a);
                            a = fmaf(Lv[i].y, r.y, a);
                            a = fmaf(Lv[i].z, r.z, a);
                            a = fmaf(Lv[i].w, r.w, a);
                            acc[i][dd] = a;
                        }
                    }
                }
            }
        }
    }

    if (act)
        #pragma unroll
        for (int i = 0; i < 8; i++)
            #pragma unroll
            for (int dd = 0; dd < 7; dd++)
                cost[(dbase + dd) * STRD + (x0 + i)] = acc[i][dd];
    __syncthreads();

    // entropy ent0
    if (tid < 312) ent[tid] = col_entropy(cost, tid);
    __syncthreads();

    // stage-1: extents + prefix + refine + ent1
    extents(ent, prevv, nextv, tid);
    __syncthreads();
    prefix_scan(cost, P, segS, tid);
    if (tid < 157) {
        int x = 62 + tid;
        if (ent[x] > 0.6f) {
            int a, bb; get_ab(prevv, nextv, x, a, bb);
            float invd = 1.0f / (float)(bb - a + 1);
            for (int d = 0; d <= 48; d++)
                cost[d * STRD + x] = (P[d * STRD + bb] - P[d * STRD + a - 1]) * invd;
            ent[x] = col_entropy(cost, x);
        }
    }
    __syncthreads();

    // stage-2: extents + prefix + teacher + loss
    extents(ent, prevv, nextv, tid);
    __syncthreads();
    prefix_scan(cost, P, segS, tid);

    float lnum = 0.f, lcnt = 0.f;
    if (tid < 157) {
        int x = 62 + tid;
        if (ent[x] > 0.6f) {
            int a, bb; get_ab(prevv, nextv, x, a, bb);
            float best = -3.4e38f; int bd = 0;
            for (int d = 0; d <= 48; d++) {
                float nm = P[d * STRD + bb] - P[d * STRD + a - 1];
                if (nm > best) { best = nm; bd = d; }
            }
            float ad = fabsf(stuRow[x] * 0.25f - (float)bd);
            lnum = (ad < 1.f) ? 0.5f * ad * ad : ad - 0.5f;
            lcnt = 1.f;
        }
    }
    int wid = tid >> 5, lane = tid & 31;
    #pragma unroll
    for (int o = 16; o; o >>= 1) {
        lnum += __shfl_down_sync(0xffffffffu, lnum, o);
        lcnt += __shfl_down_sync(0xffffffffu, lcnt, o);
    }
    if (lane == 0) { redN[wid] = lnum; redC[wid] = lcnt; }
    __syncthreads();

    int* lastf = prevv;
    if (tid == 0) {
        float n = 0.f, c = 0.f;
        for (int w = 0; w < 10; w++) { n += redN[w]; c += redC[w]; }
        g_row[row * 2] = n; g_row[row * 2 + 1] = c;
        __threadfence();
        unsigned o = atomicInc(&g_ticket, 127u);   // wraps to 0 each replay
        lastf[0] = (o == 127u);
    }
    __syncthreads();

    if (lastf[0] && tid < 32) {
        __threadfence();
        float acc1 = 0.f;
        if (tid < 4) {
            float n = 0.f, c = 0.f;
            for (int r = tid * 32; r < tid * 32 + 32; r++) {
                n += g_row[2 * r]; c += g_row[2 * r + 1];
            }
            acc1 = n / fmaxf(c, 1.f);
        }
        acc1 += __shfl_down_sync(0xffffffffu, acc1, 2);
        acc1 += __shfl_down_sync(0xffffffffu, acc1, 1);
        if (tid == 0) out[0] = acc1 * 0.25f;
    }
}

extern "C" void kernel_launch(void* const* d_in, const int* in_sizes, int n_in,
                              void* d_out, int out_size) {
    const float* fL  = (const float*)d_in[0];
    const float* fR  = (const float*)d_in[1];
    const float* stu = (const float*)d_in[2];
    cudaFuncSetAttribute(loss_row_kernel, cudaFuncAttributeMaxDynamicSharedMemorySize, SMEM_BYTES);
    loss_row_kernel<<<128, NTHR, SMEM_BYTES>>>(fL, fR, stu, (float*)d_out);
}

// round 15
// speedup vs baseline: 1.9160x; 1.9160x over previous
#include <cuda_runtime.h>
#include <cuda_bf16.h>
#include <cstdint>

#define STRD 313
// warp-private staging: 4 bufs x 10 warps x 1792B (L 512 + R 1280)
#define OFF_STG  0
#define STG_BUF  17920
#define STG_WARP 1792
#define OFF_COST 71680
#define OFF_P    133040
#define OFF_ENT  194400
#define OFF_PREV 195680
#define OFF_NEXT 196960
#define OFF_SEG  198240
#define OFF_RED  199456
#define SMEM_BYTES 199552

#define NTHR 320

__device__ float g_row[256];
__device__ unsigned g_ticket;

__device__ __forceinline__ void cp16(uint32_t dst, const void* src) {
    asm volatile("cp.async.cg.shared.global [%0], [%1], 16;\n" :: "r"(dst), "l"(src));
}

__device__ __forceinline__ float col_entropy(const float* cost, int x) {
    int dmax = x < 48 ? x : 48;
    const float* c = cost + x;
    float m = c[0];
    for (int d = 1; d <= dmax; d++) m = fmaxf(m, c[d * STRD]);
    float S = 0.f;
    for (int d = 0; d <= dmax; d++) S += expf((c[d * STRD] - m) * 10.0f);
    float logS = logf(S), invS = 1.0f / S;
    float thr = logS - 18.420681f;
    float acc = 0.f;
    for (int d = 0; d <= dmax; d++) {
        float l = (c[d * STRD] - m) * 10.0f;
        if (l >= thr) { float p = expf(l) * invS; acc -= p * (l - logS); }
        else acc += 1.8420681e-7f;
    }
    acc += (float)(48 - dmax) * 1.8420681e-7f;
    if (dmax == 0) return 0.f;
    float e = acc / (logf((float)(dmax + 1)) + 1e-8f);
    return fminf(1.0f, fmaxf(0.0f, e));
}

__device__ __forceinline__ void extents(const float* ent, int* prevv, int* nextv, int tid) {
    int wid = tid >> 5, lane = tid & 31;
    if (wid == 0) {
        int carry = -1;
        for (int s = 0; s < 10; s++) {
            int idx = s * 32 + lane;
            int v = (idx < 312 && ent[idx] <= 0.6f) ? idx : -1;
            #pragma unroll
            for (int o = 1; o < 32; o <<= 1) {
                int t = __shfl_up_sync(0xffffffffu, v, o);
                if (lane >= o) v = max(v, t);
            }
            v = max(v, carry);
            if (idx < 312) prevv[idx] = v;
            carry = __shfl_sync(0xffffffffu, v, 31);
        }
    } else if (wid == 1) {
        int carry = 312;
        for (int s = 0; s < 10; s++) {
            int idx = 311 - (s * 32 + lane);
            int v = (idx >= 0 && ent[idx] <= 0.6f) ? idx : 312;
            #pragma unroll
            for (int o = 1; o < 32; o <<= 1) {
                int t = __shfl_up_sync(0xffffffffu, v, o);
                if (lane >= o) v = min(v, t);
            }
            v = min(v, carry);
            if (idx >= 0) nextv[idx] = v;
            carry = __shfl_sync(0xffffffffu, v, 31);
        }
    }
}

__device__ __forceinline__ void prefix_scan(const float* cost, float* P, float* segS, int tid) {
    int d = tid / 6, seg = tid - d * 6;
    if (tid < 294) {
        int xs = seg * 52;
        const float* c = cost + d * STRD;
        float* p = P + d * STRD;
        float s = 0.f;
        for (int x = xs; x < xs + 52; x++) { if (x >= d) s += c[x]; p[x] = s; }
        segS[tid] = s;
    }
    __syncthreads();
    if (tid < 294 && seg > 0) {
        float off = 0.f;
        for (int q = 0; q < seg; q++) off += segS[d * 6 + q];
        float* p = P + d * STRD;
        for (int x = seg * 52; x < seg * 52 + 52; x++) p[x] += off;
    }
    __syncthreads();
}

__device__ __forceinline__ void get_ab(const int* prevv, const int* nextv, int x, int& a, int& b) {
    int Lr = x - prevv[x] - 1; if (Lr < 0) Lr = 0;
    int Rr = nextv[x] - x - 1; if (Rr < 0) Rr = 0;
    a = x - Lr; if (a < x - 12) a = x - 12;
    b = x + Rr; if (b > x + 12) b = x + 12;
    if (b > 311) b = 311;
}

// warp-private staging of one k-slice: L rows x0w..x0w+31, R rows x0w-48..x0w+31
__device__ __forceinline__ void issue_chunk(const float* Lrow, const float* Rrow,
                                            uint32_t sb, int wid, int lane,
                                            int x0w, int k) {
    int buf = k & 3;
    uint32_t base = sb + OFF_STG + buf * STG_BUF + wid * STG_WARP;
    int xl = x0w + lane;
    if (xl < 312) cp16(base + lane * 16, Lrow + (size_t)xl * 384 + k * 4);
    #pragma unroll
    for (int t = 0; t < 3; t++) {
        int l = lane + 32 * t;
        if (l < 80) {
            int xp = x0w - 48 + l;
            if (xp >= 0 && xp < 312)
                cp16(base + 512 + l * 16, Rrow + (size_t)xp * 384 + k * 4);
        }
    }
    asm volatile("cp.async.commit_group;\n" ::: "memory");
}

__global__ void __launch_bounds__(NTHR, 1)
loss_row_kernel(const float* __restrict__ fL, const float* __restrict__ fR,
                const float* __restrict__ stu, float* __restrict__ out) {
    extern __shared__ __align__(128) char smem[];
    float* cost  = (float*)(smem + OFF_COST);
    float* P     = (float*)(smem + OFF_P);
    float* ent   = (float*)(smem + OFF_ENT);
    int*   prevv = (int*)(smem + OFF_PREV);
    int*   nextv = (int*)(smem + OFF_NEXT);
    float* segS  = (float*)(smem + OFF_SEG);
    float* redN  = (float*)(smem + OFF_RED);
    float* redC  = redN + 10;

    const int tid = threadIdx.x;
    const int row = blockIdx.x;
    const int b = row >> 5, h = 64 + (row & 31);
    const float* Lrow   = fL  + (size_t)(b * 96 + h) * (312 * 384);
    const float* Rrow   = fR  + (size_t)(b * 96 + h) * (312 * 384);
    const float* stuRow = stu + (size_t)(b * 96 + h) * 312;
    const uint32_t sb = (uint32_t)__cvta_generic_to_shared(smem);

    // warp-autonomous GEMM: lane = dgl + 8*xgl; warp owns x strip [x0w, x0w+32)
    const int wid = tid >> 5, lane = tid & 31;
    const int xgl = lane >> 3, dgl = lane & 7;
    const int x0w = wid * 32;
    const int xbase = x0w + 8 * xgl;      // thread x range: xbase..xbase+7
    const int dbase = 7 * dgl;            // dgl==7 -> d>=49, results discarded
    int l0 = 42 + 8 * xgl - 7 * dgl; if (l0 < 0) l0 = 0;

    float acc[8][7];
    #pragma unroll
    for (int i = 0; i < 8; i++)
        #pragma unroll
        for (int dd = 0; dd < 7; dd++) acc[i][dd] = 0.f;

    issue_chunk(Lrow, Rrow, sb, wid, lane, x0w, 0);
    issue_chunk(Lrow, Rrow, sb, wid, lane, x0w, 1);
    issue_chunk(Lrow, Rrow, sb, wid, lane, x0w, 2);

    for (int k = 0; k < 96; k++) {
        asm volatile("cp.async.wait_group 2;\n" ::: "memory");
        __syncwarp();
        if (k + 3 < 96) issue_chunk(Lrow, Rrow, sb, wid, lane, x0w, k + 3);
        else asm volatile("cp.async.commit_group;\n" ::: "memory");

        const char* wb = smem + OFF_STG + (k & 3) * STG_BUF + wid * STG_WARP;
        float4 Lv[8];
        #pragma unroll
        for (int i = 0; i < 8; i++)
            Lv[i] = *(const float4*)(wb + (8 * xgl + i) * 16);
        #pragma unroll
        for (int m = 0; m < 14; m++) {
            float4 r = *(const float4*)(wb + 512 + (l0 + m) * 16);
            #pragma unroll
            for (int i = 0; i < 8; i++) {
                const int dd = i - m + 6;
                if (dd >= 0 && dd < 7) {
                    float a = acc[i][dd];
                    a = fmaf(Lv[i].x, r.x, a);
                    a = fmaf(Lv[i].y, r.y, a);
                    a = fmaf(Lv[i].z, r.z, a);
                    a = fmaf(Lv[i].w, r.w, a);
                    acc[i][dd] = a;
                }
            }
        }
        __syncwarp();
    }

    #pragma unroll
    for (int i = 0; i < 8; i++)
        #pragma unroll
        for (int dd = 0; dd < 7; dd++) {
            int d = dbase + dd, x = xbase + i;
            if (d < 49 && x < 312) cost[d * STRD + x] = acc[i][dd];
        }
    __syncthreads();

    // entropy ent0
    if (tid < 312) ent[tid] = col_entropy(cost, tid);
    __syncthreads();

    // stage-1: extents + prefix + refine + ent1
    extents(ent, prevv, nextv, tid);
    __syncthreads();
    prefix_scan(cost, P, segS, tid);
    if (tid < 157) {
        int x = 62 + tid;
        if (ent[x] > 0.6f) {
            int a, bb; get_ab(prevv, nextv, x, a, bb);
            float invd = 1.0f / (float)(bb - a + 1);
            for (int d = 0; d <= 48; d++)
                cost[d * STRD + x] = (P[d * STRD + bb] - P[d * STRD + a - 1]) * invd;
            ent[x] = col_entropy(cost, x);
        }
    }
    __syncthreads();

    // stage-2: extents + prefix + teacher + loss
    extents(ent, prevv, nextv, tid);
    __syncthreads();
    prefix_scan(cost, P, segS, tid);

    float lnum = 0.f, lcnt = 0.f;
    if (tid < 157) {
        int x = 62 + tid;
        if (ent[x] > 0.6f) {
            int a, bb; get_ab(prevv, nextv, x, a, bb);
            float best = -3.4e38f; int bd = 0;
            for (int d = 0; d <= 48; d++) {
                float nm = P[d * STRD + bb] - P[d * STRD + a - 1];
                if (nm > best) { best = nm; bd = d; }
            }
            float ad = fabsf(stuRow[x] * 0.25f - (float)bd);
            lnum = (ad < 1.f) ? 0.5f * ad * ad : ad - 0.5f;
            lcnt = 1.f;
        }
    }
    #pragma unroll
    for (int o = 16; o; o >>= 1) {
        lnum += __shfl_down_sync(0xffffffffu, lnum, o);
        lcnt += __shfl_down_sync(0xffffffffu, lcnt, o);
    }
    if (lane == 0) { redN[wid] = lnum; redC[wid] = lcnt; }
    __syncthreads();

    int* lastf = prevv;
    if (tid == 0) {
        float n = 0.f, c = 0.f;
        for (int w = 0; w < 10; w++) { n += redN[w]; c += redC[w]; }
        g_row[row * 2] = n; g_row[row * 2 + 1] = c;
        __threadfence();
        unsigned o = atomicInc(&g_ticket, 127u);   // wraps to 0 each replay
        lastf[0] = (o == 127u);
    }
    __syncthreads();

    if (lastf[0] && tid < 32) {
        __threadfence();
        float acc1 = 0.f;
        if (tid < 4) {
            float n = 0.f, c = 0.f;
            for (int r = tid * 32; r < tid * 32 + 32; r++) {
                n += g_row[2 * r]; c += g_row[2 * r + 1];
            }
            acc1 = n / fmaxf(c, 1.f);
        }
        acc1 += __shfl_down_sync(0xffffffffu, acc1, 2);
        acc1 += __shfl_down_sync(0xffffffffu, acc1, 1);
        if (tid == 0) out[0] = acc1 * 0.25f;
    }
}

extern "C" void kernel_launch(void* const* d_in, const int* in_sizes, int n_in,
                              void* d_out, int out_size) {
    const float* fL  = (const float*)d_in[0];
    const float* fR  = (const float*)d_in[1];
    const float* stu = (const float*)d_in[2];
    cudaFuncSetAttribute(loss_row_kernel, cudaFuncAttributeMaxDynamicSharedMemorySize, SMEM_BYTES);
    loss_row_kernel<<<128, NTHR, SMEM_BYTES>>>(fL, fR, stu, (float*)d_out);
}